// round 4
// baseline (speedup 1.0000x reference)
#include <cuda_runtime.h>
#include <math.h>

// Problem constants
#define NC    22            // columns
#define NE    12            // embeddings per column
#define DD    64            // feature dim
#define BB    2048          // batch
#define NPAIR 231           // 22 choose 2
#define NENT  253           // 22 lin/diag entries + 231 pair entries
#define TBL   (NC*NE)       // 264 table rows per d-slice

typedef unsigned long long ull;

// ---------------- device scratch ----------------
__device__ float g_sp[NC * NE * DD];        // 0.01 * softplus(emb_std)
__device__ float g_w[DD * NENT * 8];        // per-d, per-entry lane-duplicated weights
__device__ float2 g_c[NC * NC * DD];        // linear contribution of ordered (i,j) at d
__device__ float g_partial[BB * 2 * DD];    // partial[(b*2+k)][d]

// ---------------- f32x2 packed helpers (sm_100a+) ----------------
__device__ __forceinline__ ull pack2(float lo, float hi) {
    ull r; asm("mov.b64 %0, {%1, %2};" : "=l"(r) : "f"(lo), "f"(hi)); return r;
}
__device__ __forceinline__ void unpack2(ull x, float& lo, float& hi) {
    asm("mov.b64 {%0, %1}, %2;" : "=f"(lo), "=f"(hi) : "l"(x));
}
__device__ __forceinline__ ull fma2(ull a, ull b, ull c) {
    ull r; asm("fma.rn.f32x2 %0, %1, %2, %3;" : "=l"(r) : "l"(a), "l"(b), "l"(c)); return r;
}
__device__ __forceinline__ ull mul2(ull a, ull b) {
    ull r; asm("mul.rn.f32x2 %0, %1, %2;" : "=l"(r) : "l"(a), "l"(b)); return r;
}

__device__ __forceinline__ void softmax5(const float* __restrict__ log_alpha, float* w) {
    float la[5];
    float mx = -1e30f, s = 0.f;
    #pragma unroll
    for (int z = 0; z < 5; z++) { la[z] = __ldg(log_alpha + z); mx = fmaxf(mx, la[z]); }
    #pragma unroll
    for (int z = 0; z < 5; z++) { w[z] = expf(la[z] - mx); s += w[z]; }
    float inv = 1.0f / s;
    #pragma unroll
    for (int z = 0; z < 5; z++) w[z] *= inv;
}

// ---------------- stage A: per-(i,j,d) contributions + pair weights + softplus ----
#define A_BLOCKS 121
#define SP_BLOCKS ((NC*NE*DD + 255) / 256)   // 66

__global__ void __launch_bounds__(256)
prep_a(const float* __restrict__ W_ops, const float* __restrict__ W_cat,
       const float* __restrict__ log_alpha, const float* __restrict__ emb_std) {
    if (blockIdx.x >= A_BLOCKS) {
        int t = (blockIdx.x - A_BLOCKS) * 256 + threadIdx.x;
        if (t < NC * NE * DD) {
            float x = emb_std[t];
            float sp = fmaxf(x, 0.0f) + log1pf(expf(-fabsf(x)));
            g_sp[t] = 0.01f * sp;
        }
        return;
    }
    int t = blockIdx.x * 256 + threadIdx.x;
    int d  = t & 63;
    int ij = t >> 6;
    int i = ij / NC;
    int j = ij - i * NC;

    float w[5];
    softmax5(log_alpha, w);
    const float w0 = w[0], w1 = w[1], w2 = w[2], w3 = w[3], w4 = w[4];

    const float2* W2 = reinterpret_cast<const float2*>(W_ops);
    const float2* C2 = reinterpret_cast<const float2*>(W_cat);

    float2 Pij = W2[((i*NC+j)*4 + 0)*DD + d];
    float2 Pji = W2[((j*NC+i)*4 + 0)*DD + d];
    float2 Xij = W2[((i*NC+j)*4 + 2)*DD + d];
    float2 Xji = W2[((j*NC+i)*4 + 2)*DD + d];
    float2 Nij = W2[((i*NC+j)*4 + 3)*DD + d];
    float2 Nji = W2[((j*NC+i)*4 + 3)*DD + d];
    float2 Cp  = C2[(i*NC+j)*(2*DD) + d];        // p half, row d
    float2 Cq  = C2[(j*NC+i)*(2*DD) + DD + d];   // q half, row 64+d

    float c0 = w0*(Pij.x+Pji.x) + 0.5f*w2*(Xij.x+Xji.x)
             + 0.5f*w3*(Nij.x+Nji.x) + w4*(Cp.x+Cq.x);
    float c1 = w0*(Pij.y+Pji.y) + 0.5f*w2*(Xij.y+Xji.y)
             + 0.5f*w3*(Nij.y+Nji.y) + w4*(Cp.y+Cq.y);
    g_c[(i*NC + j)*DD + d] = make_float2(c0, c1);

    if (i == j) {
        float2 Mii = W2[((i*NC+i)*4 + 1)*DD + d];
        float4* dst = reinterpret_cast<float4*>(g_w + (d*NENT + i)*8);
        dst[1] = make_float4(w1*Mii.x, w1*Mii.x, w1*Mii.y, w1*Mii.y);
    } else if (i < j) {
        float2 Mij = W2[((i*NC+j)*4 + 1)*DD + d];
        float2 Mji = W2[((j*NC+i)*4 + 1)*DD + d];
        float wx = w1*(Mij.x+Mji.x);
        float wy = w1*(Mij.y+Mji.y);
        float wz = 0.5f*(w2*(Xij.x+Xji.x) - w3*(Nij.x+Nji.x));
        float ww = 0.5f*(w2*(Xij.y+Xji.y) - w3*(Nij.y+Nji.y));
        int entry = NC + (i*(2*NC - 1 - i))/2 + (j - i - 1);
        float4* dst = reinterpret_cast<float4*>(g_w + (d*NENT + entry)*8);
        dst[0] = make_float4(wx, wx, wy, wy);
        dst[1] = make_float4(wz, wz, ww, ww);
    }
}

// ---------------- stage 1: fused main kernel -------------------------------------
// grid: (BB/128) x DD, 64 threads. Prologue also performs the old prep_b
// (linear-weight reduction over j) directly into shared memory.
__global__ void __launch_bounds__(64)
main_kernel(const int* __restrict__ idx, const float* __restrict__ emb_mean,
            const float* __restrict__ v) {
    const int d  = blockIdx.y;
    const int b0 = blockIdx.x * 128;
    const int tid = threadIdx.x;

    __shared__ float swt[NENT * 8];     // duplicated weights
    __shared__ float mean_s[TBL];       // per-d embedding-mean slice
    __shared__ float sp_s[TBL];         // per-d softplus slice

    {
        // pair + diag weights from g_w (entries 0..21 dst[1], 22..252 both)
        const float4* wp = reinterpret_cast<const float4*>(g_w + d * NENT * 8);
        float4* s4 = reinterpret_cast<float4*>(swt);
        #pragma unroll 4
        for (int t = tid; t < NENT * 2; t += 64) s4[t] = wp[t];
        for (int t = tid; t < TBL; t += 64) {
            mean_s[t] = emb_mean[t * DD + d];
            sp_s[t]   = g_sp[t * DD + d];
        }
        // fused prep_b: linear weights for this d
        if (tid < NC) {
            float l0 = 0.f, l1 = 0.f;
            #pragma unroll
            for (int j = 0; j < NC; j++) {
                float2 c = g_c[(tid*NC + j)*DD + d];
                l0 += c.x; l1 += c.y;
            }
            reinterpret_cast<float4*>(swt)[tid * 2] = make_float4(l0, l0, l1, l1);
        }
    }
    __syncthreads();

    const int b  = b0 + tid;
    const int b2 = b + 64;
    const float vlo = v[b  * DD + d];
    const float vhi = v[b2 * DD + d];

    ull e2[NC];
    #pragma unroll
    for (int i = 0; i < NC; i++) {
        int iv  = idx[i * BB + b];
        int iv2 = idx[i * BB + b2];
        float elo = fmaf(sp_s[i * NE + iv],  vlo, mean_s[i * NE + iv]);
        float ehi = fmaf(sp_s[i * NE + iv2], vhi, mean_s[i * NE + iv2]);
        e2[i] = pack2(elo, ehi);
    }

    ull A0 = 0ULL, A1 = 0ULL;
    const ulonglong2* sw2 = reinterpret_cast<const ulonglong2*>(swt);

    #pragma unroll
    for (int i = 0; i < NC; i++) {
        ulonglong2 wl = sw2[i * 2 + 0];
        ulonglong2 wd = sw2[i * 2 + 1];
        ull p2 = mul2(e2[i], e2[i]);
        A0 = fma2(e2[i], wl.x, A0);
        A1 = fma2(e2[i], wl.y, A1);
        A0 = fma2(p2,    wd.x, A0);
        A1 = fma2(p2,    wd.y, A1);
    }

    const ull NEG1 = 0xBF800000BF800000ULL;
    int pi = NC;
    #pragma unroll
    for (int i = 0; i < NC - 1; i++) {
        #pragma unroll
        for (int j = i + 1; j < NC; j++) {
            ulonglong2 wm = sw2[pi * 2 + 0];
            ulonglong2 wa = sw2[pi * 2 + 1];
            pi++;
            ull p2 = mul2(e2[i], e2[j]);
            ull df = fma2(e2[j], NEG1, e2[i]);
            ull ad = df & 0x7FFFFFFF7FFFFFFFULL;
            A0 = fma2(p2, wm.x, A0);
            A1 = fma2(p2, wm.y, A1);
            A0 = fma2(ad, wa.x, A0);
            A1 = fma2(ad, wa.y, A1);
        }
    }

    float a0l, a0h, a1l, a1h;
    unpack2(A0, a0l, a0h);
    unpack2(A1, a1l, a1h);
    // layout: partial[(b*2+k)][d]  (coalesced for the reduce kernel)
    g_partial[(b  * 2 + 0) * DD + d] = a0l;
    g_partial[(b  * 2 + 1) * DD + d] = a1l;
    g_partial[(b2 * 2 + 0) * DD + d] = a0h;
    g_partial[(b2 * 2 + 1) * DD + d] = a1h;
}

// ---------------- stage 2: warp-per-output reduce over d --------------------------
// 4096 outputs; one warp each; 512 blocks x 256 threads (8 warps)
__global__ void __launch_bounds__(256)
reduce_kernel(float* __restrict__ out) {
    int warp = (blockIdx.x * 256 + threadIdx.x) >> 5;   // 0..4095
    int lane = threadIdx.x & 31;
    const float* p = g_partial + warp * DD;
    float s = p[lane] + p[lane + 32];
    #pragma unroll
    for (int o = 16; o > 0; o >>= 1)
        s += __shfl_down_sync(0xFFFFFFFFu, s, o);
    if (lane == 0) out[warp] = s;
}

// ---------------- launch ----------------------------------------------------------
extern "C" void kernel_launch(void* const* d_in, const int* in_sizes, int n_in,
                              void* d_out, int out_size) {
    const int*   idx       = (const int*)  d_in[0];
    const float* emb_mean  = (const float*)d_in[1];
    const float* emb_std   = (const float*)d_in[2];
    const float* v         = (const float*)d_in[3];
    const float* W_ops     = (const float*)d_in[4];
    const float* W_cat     = (const float*)d_in[5];
    const float* log_alpha = (const float*)d_in[6];
    float* out = (float*)d_out;

    prep_a<<<A_BLOCKS + SP_BLOCKS, 256>>>(W_ops, W_cat, log_alpha, emb_std);
    main_kernel<<<dim3(BB / 128, DD), 64>>>(idx, emb_mean, v);
    reduce_kernel<<<(BB * 2) / 8, 256>>>(out);
}